// round 10
// baseline (speedup 1.0000x reference)
#include <cuda_runtime.h>
#include <cstdint>

// TokenBladeBank: FNV-1a 4-gram hash -> gather from 8 blade banks.
// token_window: (8, 8192, 4) int32 OR int64 (runtime-detected)
// bank:         (8, 500000, 16) float32
// out:          (8, 8192, 8, 16) float32  ->  out[pos*128 + blade*16 + d]
//
// R5 structure (best: 13.1us) with the register budget opened up:
// ncu showed regs=32, which cannot hold 8 in-flight float4 gather results —
// ptxas was serializing the load batch into waves (MLP_eff ~4).
// __launch_bounds__(128, 8) raises the budget to ~64 regs so all 8 gathers
// are truly outstanding (front-batched LDGs), trading occupancy (70%->50%)
// for +40% in-flight read bytes per SM. No cache-policy hints (regressed in
// R4/R7/R8): plain __ldg loads + __stcs streaming stores.

#define TBB_N_SLOTS    500000u
#define TBB_FNV_OFFSET 2166136261u
#define TBB_FNV_PRIME  16777619u
#define TBB_POS_PER_WARP 8

// 1 = tokens are int32 words, 2 = tokens are int64 (read LE low half).
__device__ int g_tok_stride;

__global__ void tbb_detect_kernel(const unsigned* __restrict__ tw)
{
    unsigned acc = 0;
    #pragma unroll
    for (int i = 1; i < 64; i += 2) acc |= tw[i];
    g_tok_stride = (acc == 0) ? 2 : 1;
}

__device__ __forceinline__ unsigned tbb_fnv4(unsigned a, unsigned b,
                                             unsigned c, unsigned d)
{
    unsigned h = TBB_FNV_OFFSET;
    h = (h ^ a) * TBB_FNV_PRIME;
    h = (h ^ b) * TBB_FNV_PRIME;
    h = (h ^ c) * TBB_FNV_PRIME;
    h = (h ^ d) * TBB_FNV_PRIME;
    return h % TBB_N_SLOTS;
}

__global__ void __launch_bounds__(128, 8)   // <=64 regs: keep 8 loads in flight
tbb_gather_kernel(const unsigned* __restrict__ tw,
                  const float4*  __restrict__ bank,
                  float4*        __restrict__ out,
                  int n_pos)
{
    const int t    = blockIdx.x * blockDim.x + threadIdx.x;
    const int warp = t >> 5;
    const int lane = t & 31;
    const int pos0 = warp * TBB_POS_PER_WARP;
    if (pos0 >= n_pos) return;

    const int stride = g_tok_stride;              // uniform broadcast load
    const unsigned blade = (unsigned)lane >> 2;   // 0..7
    const unsigned q     = (unsigned)lane & 3;    // float4 within 16-fp row
    const int      sub   = lane & 7;              // which position I hash

    const uint4* tw4 = (const uint4*)tw;

    // Each lane hashes ONE position (pos0+sub); width-8 shuffles broadcast
    // all 8 addresses to every lane.
    unsigned myaddr;
    if (stride == 1) {
        uint4 tk = __ldg(&tw4[pos0 + sub]);
        myaddr = tbb_fnv4(tk.x, tk.y, tk.z, tk.w);
    } else {
        const size_t p = (size_t)(pos0 + sub) * 2;
        uint4 ta = __ldg(&tw4[p]);
        uint4 tb = __ldg(&tw4[p + 1]);
        myaddr = tbb_fnv4(ta.x, ta.z, tb.x, tb.z);
    }

    // Precompute all 8 gather pointers first (pure ALU after shuffles).
    const float4* ptr[TBB_POS_PER_WARP];
    #pragma unroll
    for (int g = 0; g < TBB_POS_PER_WARP; g++) {
        const unsigned a = __shfl_sync(0xffffffffu, myaddr, g, 8);
        ptr[g] = &bank[((size_t)blade * TBB_N_SLOTS + (size_t)a) * 4 + q];
    }

    // 8 independent random 16 B gathers, front-batched (true MLP=8).
    // Lanes 4b..4b+3 cover one contiguous 64 B row: perfect sector use.
    float4 v[TBB_POS_PER_WARP];
    #pragma unroll
    for (int g = 0; g < TBB_POS_PER_WARP; g++)
        v[g] = __ldg(ptr[g]);

    // 8 coalesced 512 B streaming stores -> 4 KB contiguous per warp.
    #pragma unroll
    for (int g = 0; g < TBB_POS_PER_WARP; g++)
        __stcs(&out[(size_t)(pos0 + g) * 32 + lane], v[g]);
}

extern "C" void kernel_launch(void* const* d_in, const int* in_sizes, int n_in,
                              void* d_out, int out_size)
{
    const unsigned* tw   = (const unsigned*)d_in[0];
    const float4*   bank = (const float4*)d_in[1];
    float4*         out  = (float4*)d_out;

    const int n_pos = in_sizes[0] / 4;            // 65536 positions

    tbb_detect_kernel<<<1, 1>>>(tw);

    const int threads = 128;
    const int warps   = (n_pos + TBB_POS_PER_WARP - 1) / TBB_POS_PER_WARP;
    const int blocks  = (warps * 32 + threads - 1) / threads;  // 2048
    tbb_gather_kernel<<<blocks, threads>>>(tw, bank, out, n_pos);
}

// round 11
// speedup vs baseline: 1.1834x; 1.1834x over previous
#include <cuda_runtime.h>
#include <cstdint>

// TokenBladeBank: FNV-1a 4-gram hash -> gather from 8 blade banks.
// token_window: (8, 8192, 4) int32 OR int64 (detected in-warp)
// bank:         (8, 500000, 16) float32
// out:          (8, 8192, 8, 16) float32  ->  out[pos*128 + blade*16 + d]
//
// Single-node version of the best kernel (R5, 13.1us): the separate 1-thread
// dtype-detect kernel cost ~2us of serial graph time. Detection is now done
// per-warp: each lane reads one odd 32-bit word of the first 64 token words
// (256B, L2-broadcast across all warps); int64 LE layout => all odd words are
// zero high-halves => ballot==0 => stride 2. Gather structure unchanged:
// 8 pos/warp, width-8 shuffle-shared hashing, 8 front-batched float4 __ldg
// gathers (each 64B row covered by 4 lanes = 2 full sectors), __stcs
// streaming stores (4KB contiguous per warp).

#define TBB_N_SLOTS    500000u
#define TBB_FNV_OFFSET 2166136261u
#define TBB_FNV_PRIME  16777619u
#define TBB_POS_PER_WARP 8

__device__ __forceinline__ unsigned tbb_fnv4(unsigned a, unsigned b,
                                             unsigned c, unsigned d)
{
    unsigned h = TBB_FNV_OFFSET;
    h = (h ^ a) * TBB_FNV_PRIME;
    h = (h ^ b) * TBB_FNV_PRIME;
    h = (h ^ c) * TBB_FNV_PRIME;
    h = (h ^ d) * TBB_FNV_PRIME;
    return h % TBB_N_SLOTS;
}

__global__ void __launch_bounds__(128)
tbb_gather_kernel(const unsigned* __restrict__ tw,
                  const float4*  __restrict__ bank,
                  float4*        __restrict__ out,
                  int n_pos)
{
    const int t    = blockIdx.x * blockDim.x + threadIdx.x;
    const int warp = t >> 5;
    const int lane = t & 31;
    const int pos0 = warp * TBB_POS_PER_WARP;
    if (pos0 >= n_pos) return;

    // In-warp dtype detection: odd 32-bit words of the first 64 token words.
    // int64 little-endian layout => all are zero high-halves (tokens < 50257);
    // int32 layout => they are random tokens, P(all 32 == 0) ~ 50257^-32 ~ 0.
    const unsigned probe = __ldg(&tw[2 * lane + 1]);
    const unsigned nz    = __ballot_sync(0xffffffffu, probe != 0u);
    const int stride     = (nz == 0u) ? 2 : 1;

    const unsigned blade = (unsigned)lane >> 2;   // 0..7
    const unsigned q     = (unsigned)lane & 3;    // float4 within 16-fp row
    const int      sub   = lane & 7;              // which position I hash

    const uint4* tw4 = (const uint4*)tw;

    // Each lane hashes ONE position (pos0+sub); width-8 shuffles broadcast
    // all 8 addresses to every lane.
    unsigned myaddr;
    if (stride == 1) {
        uint4 tk = __ldg(&tw4[pos0 + sub]);
        myaddr = tbb_fnv4(tk.x, tk.y, tk.z, tk.w);
    } else {
        const size_t p = (size_t)(pos0 + sub) * 2;
        uint4 ta = __ldg(&tw4[p]);
        uint4 tb = __ldg(&tw4[p + 1]);
        myaddr = tbb_fnv4(ta.x, ta.z, tb.x, tb.z);
    }

    unsigned addr[TBB_POS_PER_WARP];
    #pragma unroll
    for (int g = 0; g < TBB_POS_PER_WARP; g++)
        addr[g] = __shfl_sync(0xffffffffu, myaddr, g, 8);

    // 8 independent random 16 B gathers (MLP=8).
    // Lanes 4b..4b+3 cover one contiguous 64 B row: perfect sector use.
    float4 v[TBB_POS_PER_WARP];
    #pragma unroll
    for (int g = 0; g < TBB_POS_PER_WARP; g++) {
        const size_t bidx =
            ((size_t)blade * TBB_N_SLOTS + (size_t)addr[g]) * 4 + q;
        v[g] = __ldg(&bank[bidx]);
    }

    // 8 coalesced 512 B streaming stores -> 4 KB contiguous per warp.
    #pragma unroll
    for (int g = 0; g < TBB_POS_PER_WARP; g++)
        __stcs(&out[(size_t)(pos0 + g) * 32 + lane], v[g]);
}

extern "C" void kernel_launch(void* const* d_in, const int* in_sizes, int n_in,
                              void* d_out, int out_size)
{
    const unsigned* tw   = (const unsigned*)d_in[0];
    const float4*   bank = (const float4*)d_in[1];
    float4*         out  = (float4*)d_out;

    const int n_pos = out_size / 128;             // 65536 positions (dtype-proof)

    const int threads = 128;
    const int warps   = (n_pos + TBB_POS_PER_WARP - 1) / TBB_POS_PER_WARP;
    const int blocks  = (warps * 32 + threads - 1) / threads;  // 2048
    tbb_gather_kernel<<<blocks, threads>>>(tw, bank, out, n_pos);
}